// round 8
// baseline (speedup 1.0000x reference)
#include <cuda_runtime.h>
#include <cstdint>

// SDF_75806172774865 — R8: R6 pipeline (depth-2 cp.async, 2-barrier loop),
// SLAB=12 -> 40.6KB smem -> 5 blocks/SM (40 warps). launch_bounds(256,5).
// points: (N,P,3) f32 ; v,vn: (N,P,K,3) f32 ; sr: (N,P,K) f32 ; out: (N,) f32

#define K_FIX 60
#define SLAB 12                        // points per slab (2 per warp, warps 0-5)
#define THREADS 256
#define NWARPS 8
#define ROWF (K_FIX * 3)               // 180 floats per v/vn row
#define OFF_VN (SLAB * ROWF)           // 2160
#define OFF_SR (2 * SLAB * ROWF)       // 4320
#define OFF_PT (OFF_SR + SLAB * K_FIX) // 5040
#define BUF_FLOATS (OFF_PT + SLAB * 3) // 5076 floats = 20304 B
#define V4  (SLAB * ROWF / 4)          // 540 float4 for v (and vn)
#define SR4 (SLAB * K_FIX / 4)         // 180
#define PT4 (SLAB * 3 / 4)             // 9
#define NMAX 8

__device__ __forceinline__ void cp_async16(void* smem_ptr, const void* gptr) {
    uint32_t sa = (uint32_t)__cvta_generic_to_shared(smem_ptr);
    asm volatile("cp.async.cg.shared.global [%0], [%1], 16;" :: "r"(sa), "l"(gptr));
}
#define CP_COMMIT() asm volatile("cp.async.commit_group;")
#define CP_WAIT1()  asm volatile("cp.async.wait_group 1;")
#define CP_WAIT0()  asm volatile("cp.async.wait_group 0;")

__global__ void sdf_zero_kernel(float* __restrict__ out, int n) {
    int i = blockIdx.x * blockDim.x + threadIdx.x;
    if (i < n) out[i] = 0.0f;
}

__device__ __forceinline__ void stage_slab(
    float* __restrict__ buf,
    const float* __restrict__ v, const float* __restrict__ vn,
    const float* __restrict__ sr, const float* __restrict__ points,
    int slab, int tid, int total_points)
{
    const int gp0 = slab * SLAB;
    const float4* gv  = (const float4*)(v      + (size_t)gp0 * ROWF);
    const float4* gvn = (const float4*)(vn     + (size_t)gp0 * ROWF);
    const float4* gsr = (const float4*)(sr     + (size_t)gp0 * K_FIX);
    const float4* gpt = (const float4*)(points + (size_t)gp0 * 3);
    float4* sv  = (float4*)buf;
    float4* svn = (float4*)(buf + OFF_VN);
    float4* ssr = (float4*)(buf + OFF_SR);
    float4* spt = (float4*)(buf + OFF_PT);

    const int npts = min(SLAB, total_points - gp0);
    if (npts == SLAB) {
        #pragma unroll
        for (int it = 0; it < 3; it++) {
            const int i = tid + it * THREADS;
            if (i < V4) cp_async16(sv + i, gv + i);
        }
        #pragma unroll
        for (int it = 0; it < 3; it++) {
            const int i = tid + it * THREADS;
            if (i < V4) cp_async16(svn + i, gvn + i);
        }
        if (tid < SR4) cp_async16(ssr + tid, gsr + tid);
        if (tid < PT4) cp_async16(spt + tid, gpt + tid);
    } else {
        const int nv4  = npts * (ROWF / 4);
        const int nsr4 = npts * (K_FIX / 4);
        const int npt4 = (npts * 3 + 3) / 4;
        #pragma unroll
        for (int it = 0; it < 3; it++) {
            const int i = tid + it * THREADS;
            if (i < nv4) { cp_async16(sv + i, gv + i); cp_async16(svn + i, gvn + i); }
        }
        if (tid < nsr4) cp_async16(ssr + tid, gsr + tid);
        if (tid < npt4) cp_async16(spt + tid, gpt + tid);
    }
}

__device__ __forceinline__ void kstep(float px, float py, float pz,
                                      float vx, float vy, float vz,
                                      float nx, float ny, float nz, float s,
                                      float& num, float& den) {
    const float dx = px - vx;
    const float dy = py - vy;
    const float dz = pz - vz;
    const float d2 = fmaf(dx, dx, fmaf(dy, dy, dz * dz));
    const float w  = 1.0f - d2 * __frcp_rn(s);
    const float w2 = w * w;
    const float phi = (d2 < s) ? (w2 * w2) : 1e-18f;
    const float dot = fmaf(nx, dx, fmaf(ny, dy, nz * dz));
    num = fmaf(phi, dot, num);
    den += phi;
}

__global__ __launch_bounds__(THREADS, 5)
void sdf_kernel(const float* __restrict__ points,
                const float* __restrict__ v,
                const float* __restrict__ vn,
                const float* __restrict__ sr,
                float* __restrict__ out,
                int total_points, int P, int N,
                int total_slabs, int spb_lo, int extra) {
    __shared__ __align__(16) float s_buf[2][BUF_FLOATS];
    __shared__ float s_acc[NWARPS * NMAX];

    const int tid  = threadIdx.x;
    const int warp = tid >> 5;
    const int lane = tid & 31;
    const int half = lane >> 4;    // 0: point 2w, 1: point 2w+1
    const int sub  = lane & 15;    // 0..14 active (4 ks each), 15 idle

    // Balanced distribution: block b handles cnt = spb_lo + (b < extra) slabs.
    const int b_id = blockIdx.x;
    const int s0 = b_id * spb_lo + min(b_id, extra);
    const int cnt = spb_lo + (b_id < extra ? 1 : 0);
    const int s1 = s0 + cnt;
    if (cnt <= 0) return;

    if (tid < NWARPS * NMAX) s_acc[tid] = 0.0f;

    stage_slab(s_buf[s0 & 1], v, vn, sr, points, s0, tid, total_points);
    CP_COMMIT();

    for (int s = s0; s < s1; s++) {
        const int cur = s & 1;
        __syncthreads();                 // compute on buf[cur^1] done
        if (s + 1 < s1) {
            stage_slab(s_buf[cur ^ 1], v, vn, sr, points, s + 1, tid, total_points);
            CP_COMMIT();
            CP_WAIT1();                  // slab s resident
        } else {
            CP_WAIT0();
        }
        __syncthreads();

        const float* __restrict__ buf = s_buf[cur];
        const int p  = 2 * warp + half;          // 0..11 valid (warps 0..5)
        const int gp = s * SLAB + p;
        const bool pvalid = (warp < SLAB / 2) && (gp < total_points);

        float num = 0.0f, den = 0.0f;
        if (pvalid && sub < 15) {
            const float* __restrict__ vrow  = buf + p * ROWF  + sub * 12;
            const float* __restrict__ vnrow = buf + OFF_VN + p * ROWF  + sub * 12;
            const float* __restrict__ srow  = buf + OFF_SR + p * K_FIX + sub * 4;
            const float* __restrict__ prow  = buf + OFF_PT + p * 3;
            const float px = prow[0], py = prow[1], pz = prow[2];

            const float4 s4 = *(const float4*)srow;
            const float4 va = *(const float4*)(vrow);
            const float4 vb = *(const float4*)(vrow + 4);
            const float4 na = *(const float4*)(vnrow);
            const float4 nb = *(const float4*)(vnrow + 4);
            kstep(px, py, pz, va.x, va.y, va.z, na.x, na.y, na.z, s4.x, num, den);
            kstep(px, py, pz, va.w, vb.x, vb.y, na.w, nb.x, nb.y, s4.y, num, den);
            const float4 vc = *(const float4*)(vrow + 8);
            const float4 nc = *(const float4*)(vnrow + 8);
            kstep(px, py, pz, vb.z, vb.w, vc.x, nb.z, nb.w, nc.x, s4.z, num, den);
            kstep(px, py, pz, vc.y, vc.z, vc.w, nc.y, nc.z, nc.w, s4.w, num, den);
        }

        if (warp < SLAB / 2) {
            #pragma unroll
            for (int o = 8; o > 0; o >>= 1) {
                num += __shfl_xor_sync(0xffffffffu, num, o);
                den += __shfl_xor_sync(0xffffffffu, den, o);
            }
            const float sdf   = fdividef(num, den);
            const float sdf2  = pvalid ? (sdf * sdf) : 0.0f;
            const float sdf2B = __shfl_sync(0xffffffffu, sdf2, 16);

            if (lane == 0) {
                const int gpA = s * SLAB + 2 * warp;
                if (gpA < total_points) {
                    int niA = 0;
                    while (gpA >= (niA + 1) * P) niA++;
                    float add = sdf2;
                    if (gpA + 1 < total_points) {
                        const int niB = niA + ((gpA + 1) >= (niA + 1) * P ? 1 : 0);
                        if (niB == niA) add += sdf2B;
                        else s_acc[warp * NMAX + niB] += sdf2B;
                    }
                    s_acc[warp * NMAX + niA] += add;
                }
            }
        }
    }

    __syncthreads();
    if (tid < N && tid < NMAX) {
        float sum = 0.0f;
        #pragma unroll
        for (int w = 0; w < NWARPS; w++) sum += s_acc[w * NMAX + tid];
        atomicAdd(&out[tid], sum);
    }
}

extern "C" void kernel_launch(void* const* d_in, const int* in_sizes, int n_in,
                              void* d_out, int out_size) {
    const float* points = (const float*)d_in[0];
    const float* v      = (const float*)d_in[1];
    const float* vn     = (const float*)d_in[2];
    const float* sr     = (const float*)d_in[3];
    float* out = (float*)d_out;

    const int total_points = in_sizes[0] / 3;  // N*P
    const int N = out_size;
    const int P = total_points / N;

    sdf_zero_kernel<<<1, 32>>>(out, out_size);

    const int total_slabs = (total_points + SLAB - 1) / SLAB;
    const int max_blocks  = 148 * 5;           // 5 blocks/SM (smem-limited)
    const int grid        = total_slabs < max_blocks ? total_slabs : max_blocks;
    const int spb_lo      = total_slabs / grid;
    const int extra       = total_slabs - spb_lo * grid;

    sdf_kernel<<<grid, THREADS>>>(points, v, vn, sr, out,
                                  total_points, P, N, total_slabs, spb_lo, extra);
}

// round 9
// speedup vs baseline: 1.4545x; 1.4545x over previous
#include <cuda_runtime.h>
#include <cstdint>

// SDF_75806172774865 — R9: exact R6 config (best: 57.8us) + balanced slab
// distribution. SLAB=16, depth-2 cp.async, 2-pts/warp LDS.128 compute,
// launch_bounds(256,4), 54KB smem -> 4 blocks/SM.
// points: (N,P,3) f32 ; v,vn: (N,P,K,3) f32 ; sr: (N,P,K) f32 ; out: (N,) f32

#define K_FIX 60
#define SLAB 16                        // points per slab (2 per warp)
#define THREADS 256
#define NWARPS 8
#define ROWF (K_FIX * 3)               // 180 floats per v/vn row
#define OFF_VN (SLAB * ROWF)           // 2880
#define OFF_SR (2 * SLAB * ROWF)       // 5760
#define OFF_PT (OFF_SR + SLAB * K_FIX) // 6720
#define BUF_FLOATS (OFF_PT + SLAB * 3) // 6768 floats = 27072 B
#define V4  (SLAB * ROWF / 4)          // 720 float4 per slab for v (and vn)
#define SR4 (SLAB * K_FIX / 4)         // 240
#define PT4 (SLAB * 3 / 4)             // 12
#define NMAX 8

__device__ __forceinline__ void cp_async16(void* smem_ptr, const void* gptr) {
    uint32_t sa = (uint32_t)__cvta_generic_to_shared(smem_ptr);
    asm volatile("cp.async.cg.shared.global [%0], [%1], 16;" :: "r"(sa), "l"(gptr));
}
#define CP_COMMIT() asm volatile("cp.async.commit_group;")
#define CP_WAIT1()  asm volatile("cp.async.wait_group 1;")
#define CP_WAIT0()  asm volatile("cp.async.wait_group 0;")

__global__ void sdf_zero_kernel(float* __restrict__ out, int n) {
    int i = blockIdx.x * blockDim.x + threadIdx.x;
    if (i < n) out[i] = 0.0f;
}

__device__ __forceinline__ void stage_slab(
    float* __restrict__ buf,
    const float* __restrict__ v, const float* __restrict__ vn,
    const float* __restrict__ sr, const float* __restrict__ points,
    int slab, int tid, int total_points)
{
    const int gp0 = slab * SLAB;
    const float4* gv  = (const float4*)(v      + (size_t)gp0 * ROWF);
    const float4* gvn = (const float4*)(vn     + (size_t)gp0 * ROWF);
    const float4* gsr = (const float4*)(sr     + (size_t)gp0 * K_FIX);
    const float4* gpt = (const float4*)(points + (size_t)gp0 * 3);
    float4* sv  = (float4*)buf;
    float4* svn = (float4*)(buf + OFF_VN);
    float4* ssr = (float4*)(buf + OFF_SR);
    float4* spt = (float4*)(buf + OFF_PT);

    const int npts = min(SLAB, total_points - gp0);
    if (npts == SLAB) {
        #pragma unroll
        for (int it = 0; it < 3; it++) {
            const int i = tid + it * THREADS;
            if (i < V4) cp_async16(sv + i, gv + i);
        }
        #pragma unroll
        for (int it = 0; it < 3; it++) {
            const int i = tid + it * THREADS;
            if (i < V4) cp_async16(svn + i, gvn + i);
        }
        if (tid < SR4) cp_async16(ssr + tid, gsr + tid);
        if (tid < PT4) cp_async16(spt + tid, gpt + tid);
    } else {
        const int nv4  = npts * (ROWF / 4);
        const int nsr4 = npts * (K_FIX / 4);
        const int npt4 = (npts * 3 + 3) / 4;
        #pragma unroll
        for (int it = 0; it < 3; it++) {
            const int i = tid + it * THREADS;
            if (i < nv4) { cp_async16(sv + i, gv + i); cp_async16(svn + i, gvn + i); }
        }
        if (tid < nsr4) cp_async16(ssr + tid, gsr + tid);
        if (tid < npt4) cp_async16(spt + tid, gpt + tid);
    }
}

__device__ __forceinline__ void kstep(float px, float py, float pz,
                                      float vx, float vy, float vz,
                                      float nx, float ny, float nz, float s,
                                      float& num, float& den) {
    const float dx = px - vx;
    const float dy = py - vy;
    const float dz = pz - vz;
    const float d2 = fmaf(dx, dx, fmaf(dy, dy, dz * dz));
    const float w  = 1.0f - d2 * __frcp_rn(s);
    const float w2 = w * w;
    const float phi = (d2 < s) ? (w2 * w2) : 1e-18f;
    const float dot = fmaf(nx, dx, fmaf(ny, dy, nz * dz));
    num = fmaf(phi, dot, num);
    den += phi;
}

__global__ __launch_bounds__(THREADS, 4)
void sdf_kernel(const float* __restrict__ points,
                const float* __restrict__ v,
                const float* __restrict__ vn,
                const float* __restrict__ sr,
                float* __restrict__ out,
                int total_points, int P, int N,
                int spb_lo, int extra) {
    __shared__ __align__(16) float s_buf[2][BUF_FLOATS];
    __shared__ float s_acc[NWARPS * NMAX];

    const int tid  = threadIdx.x;
    const int warp = tid >> 5;
    const int lane = tid & 31;
    const int half = lane >> 4;    // 0: point 2w, 1: point 2w+1
    const int sub  = lane & 15;    // 0..14 active (4 ks each), 15 idle

    // Balanced distribution: block b gets spb_lo + (b < extra) slabs.
    const int b_id = blockIdx.x;
    const int s0 = b_id * spb_lo + min(b_id, extra);
    const int s1 = s0 + spb_lo + (b_id < extra ? 1 : 0);
    if (s0 >= s1) return;

    if (tid < NWARPS * NMAX) s_acc[tid] = 0.0f;

    stage_slab(s_buf[s0 & 1], v, vn, sr, points, s0, tid, total_points);
    CP_COMMIT();

    for (int s = s0; s < s1; s++) {
        const int cur = s & 1;
        __syncthreads();                 // compute on buf[cur^1] done
        if (s + 1 < s1) {
            stage_slab(s_buf[cur ^ 1], v, vn, sr, points, s + 1, tid, total_points);
            CP_COMMIT();
            CP_WAIT1();                  // slab s resident
        } else {
            CP_WAIT0();
        }
        __syncthreads();

        const float* __restrict__ buf = s_buf[cur];
        const int p   = 2 * warp + half;
        const int gp  = s * SLAB + p;
        const bool pvalid = (gp < total_points);

        float num = 0.0f, den = 0.0f;
        if (pvalid && sub < 15) {
            const float* __restrict__ vrow  = buf + p * ROWF   + sub * 12;
            const float* __restrict__ vnrow = buf + OFF_VN + p * ROWF   + sub * 12;
            const float* __restrict__ srow  = buf + OFF_SR + p * K_FIX  + sub * 4;
            const float* __restrict__ prow  = buf + OFF_PT + p * 3;
            const float px = prow[0], py = prow[1], pz = prow[2];

            const float4 s4 = *(const float4*)srow;
            const float4 va = *(const float4*)(vrow);
            const float4 vb = *(const float4*)(vrow + 4);
            const float4 na = *(const float4*)(vnrow);
            const float4 nb = *(const float4*)(vnrow + 4);
            kstep(px, py, pz, va.x, va.y, va.z, na.x, na.y, na.z, s4.x, num, den);
            kstep(px, py, pz, va.w, vb.x, vb.y, na.w, nb.x, nb.y, s4.y, num, den);
            const float4 vc = *(const float4*)(vrow + 8);
            const float4 nc = *(const float4*)(vnrow + 8);
            kstep(px, py, pz, vb.z, vb.w, vc.x, nb.z, nb.w, nc.x, s4.z, num, den);
            kstep(px, py, pz, vc.y, vc.z, vc.w, nc.y, nc.z, nc.w, s4.w, num, den);
        }

        // 16-lane half butterfly: full sums land on every lane of each half
        #pragma unroll
        for (int o = 8; o > 0; o >>= 1) {
            num += __shfl_xor_sync(0xffffffffu, num, o);
            den += __shfl_xor_sync(0xffffffffu, den, o);
        }
        const float sdf  = fdividef(num, den);
        const float sdf2 = pvalid ? (sdf * sdf) : 0.0f;
        const float sdf2B = __shfl_sync(0xffffffffu, sdf2, 16);

        if (lane == 0) {
            const int gpA = s * SLAB + 2 * warp;
            if (gpA < total_points) {
                int niA = 0;
                while (gpA >= (niA + 1) * P) niA++;
                float add = sdf2;
                if (gpA + 1 < total_points) {
                    const int niB = niA + ((gpA + 1) >= (niA + 1) * P ? 1 : 0);
                    if (niB == niA) add += sdf2B;
                    else s_acc[warp * NMAX + niB] += sdf2B;
                }
                s_acc[warp * NMAX + niA] += add;
            }
        }
    }

    __syncthreads();
    if (tid < N && tid < NMAX) {
        float sum = 0.0f;
        #pragma unroll
        for (int w = 0; w < NWARPS; w++) sum += s_acc[w * NMAX + tid];
        atomicAdd(&out[tid], sum);
    }
}

extern "C" void kernel_launch(void* const* d_in, const int* in_sizes, int n_in,
                              void* d_out, int out_size) {
    const float* points = (const float*)d_in[0];
    const float* v      = (const float*)d_in[1];
    const float* vn     = (const float*)d_in[2];
    const float* sr     = (const float*)d_in[3];
    float* out = (float*)d_out;

    const int total_points = in_sizes[0] / 3;  // N*P
    const int N = out_size;
    const int P = total_points / N;

    sdf_zero_kernel<<<1, 32>>>(out, out_size);

    const int total_slabs = (total_points + SLAB - 1) / SLAB;
    const int max_blocks  = 148 * 4;           // 4 blocks/SM (smem-limited)
    const int grid        = total_slabs < max_blocks ? total_slabs : max_blocks;
    const int spb_lo      = total_slabs / grid;
    const int extra       = total_slabs - spb_lo * grid;

    sdf_kernel<<<grid, THREADS>>>(points, v, vn, sr, out,
                                  total_points, P, N, spb_lo, extra);
}

// round 10
// speedup vs baseline: 1.5138x; 1.0407x over previous
#include <cuda_runtime.h>
#include <cstdint>

// SDF_75806172774865 — R10: barrier-free direct-LDG float4 kernel.
// Each warp: 2 points (16-lane halves); lane sub(0..14) loads 4 ks via
// 7 LDG.128 straight from global. No smem staging, no syncs in the loop.
// points: (N,P,3) f32 ; v,vn: (N,P,K,3) f32 ; sr: (N,P,K) f32 ; out: (N,) f32

#define K_FIX 60
#define THREADS 256
#define NWARPS 8
#define ROWF (K_FIX * 3)          // 180 floats per v/vn row
#define NMAX 8

__global__ void sdf_zero_kernel(float* __restrict__ out, int n) {
    int i = blockIdx.x * blockDim.x + threadIdx.x;
    if (i < n) out[i] = 0.0f;
}

__device__ __forceinline__ void kstep(float px, float py, float pz,
                                      float vx, float vy, float vz,
                                      float nx, float ny, float nz, float s,
                                      float& num, float& den) {
    const float dx = px - vx;
    const float dy = py - vy;
    const float dz = pz - vz;
    const float d2 = fmaf(dx, dx, fmaf(dy, dy, dz * dz));
    const float w  = 1.0f - d2 * __frcp_rn(s);
    const float w2 = w * w;
    const float phi = (d2 < s) ? (w2 * w2) : 1e-18f;
    const float dot = fmaf(nx, dx, fmaf(ny, dy, nz * dz));
    num = fmaf(phi, dot, num);
    den += phi;
}

__global__ __launch_bounds__(THREADS)
void sdf_kernel(const float* __restrict__ points,
                const float* __restrict__ v,
                const float* __restrict__ vn,
                const float* __restrict__ sr,
                float* __restrict__ out,
                int total_points, int P, int N,
                int ppb_lo, int extra) {   // pairs per block (balanced)
    __shared__ float s_acc[NWARPS * NMAX];

    const int tid  = threadIdx.x;
    const int warp = tid >> 5;
    const int lane = tid & 31;
    const int half = lane >> 4;    // 0: first point of pair, 1: second
    const int sub  = lane & 15;    // 0..14 active (4 ks each), 15 idle

    const int b_id = blockIdx.x;
    const int p0 = b_id * ppb_lo + min(b_id, extra);          // first pair
    const int p1 = p0 + ppb_lo + (b_id < extra ? 1 : 0);      // one past last

    if (tid < NWARPS * NMAX) s_acc[tid] = 0.0f;
    __syncthreads();

    for (int pp = p0 + warp; pp < p1; pp += NWARPS) {
        const int gp = 2 * pp + half;
        const bool pvalid = (gp < total_points);

        float num = 0.0f, den = 0.0f;
        if (pvalid && sub < 15) {
            const float* __restrict__ vrow  = v  + (size_t)gp * ROWF  + sub * 12;
            const float* __restrict__ vnrow = vn + (size_t)gp * ROWF  + sub * 12;
            const float* __restrict__ srow  = sr + (size_t)gp * K_FIX + sub * 4;
            const float* __restrict__ prow  = points + (size_t)gp * 3;

            // Issue all loads up front for max MLP.
            const float4 va = __ldg((const float4*)(vrow));
            const float4 vb = __ldg((const float4*)(vrow + 4));
            const float4 vc = __ldg((const float4*)(vrow + 8));
            const float4 na = __ldg((const float4*)(vnrow));
            const float4 nb = __ldg((const float4*)(vnrow + 4));
            const float4 nc = __ldg((const float4*)(vnrow + 8));
            const float4 s4 = __ldg((const float4*)(srow));
            const float px = __ldg(prow + 0);
            const float py = __ldg(prow + 1);
            const float pz = __ldg(prow + 2);

            kstep(px, py, pz, va.x, va.y, va.z, na.x, na.y, na.z, s4.x, num, den);
            kstep(px, py, pz, va.w, vb.x, vb.y, na.w, nb.x, nb.y, s4.y, num, den);
            kstep(px, py, pz, vb.z, vb.w, vc.x, nb.z, nb.w, nc.x, s4.z, num, den);
            kstep(px, py, pz, vc.y, vc.z, vc.w, nc.y, nc.z, nc.w, s4.w, num, den);
        }

        // 16-lane half butterfly: each half reduces its point.
        #pragma unroll
        for (int o = 8; o > 0; o >>= 1) {
            num += __shfl_xor_sync(0xffffffffu, num, o);
            den += __shfl_xor_sync(0xffffffffu, den, o);
        }
        const float sdf   = fdividef(num, den);
        const float sdf2  = pvalid ? (sdf * sdf) : 0.0f;
        const float sdf2B = __shfl_sync(0xffffffffu, sdf2, 16);

        if (lane == 0) {
            const int gpA = 2 * pp;
            if (gpA < total_points) {
                int niA = 0;
                while (gpA >= (niA + 1) * P) niA++;
                float add = sdf2;
                if (gpA + 1 < total_points) {
                    const int niB = niA + ((gpA + 1) >= (niA + 1) * P ? 1 : 0);
                    if (niB == niA) add += sdf2B;
                    else s_acc[warp * NMAX + niB] += sdf2B;
                }
                s_acc[warp * NMAX + niA] += add;
            }
        }
    }

    __syncthreads();
    if (tid < N && tid < NMAX) {
        float sum = 0.0f;
        #pragma unroll
        for (int w = 0; w < NWARPS; w++) sum += s_acc[w * NMAX + tid];
        atomicAdd(&out[tid], sum);
    }
}

extern "C" void kernel_launch(void* const* d_in, const int* in_sizes, int n_in,
                              void* d_out, int out_size) {
    const float* points = (const float*)d_in[0];
    const float* v      = (const float*)d_in[1];
    const float* vn     = (const float*)d_in[2];
    const float* sr     = (const float*)d_in[3];
    float* out = (float*)d_out;

    const int total_points = in_sizes[0] / 3;  // N*P
    const int N = out_size;
    const int P = total_points / N;

    sdf_zero_kernel<<<1, 32>>>(out, out_size);

    const int total_pairs = (total_points + 1) / 2;
    const int max_blocks  = 148 * 4;           // register-limited residency
    const int grid        = total_pairs < max_blocks ? total_pairs : max_blocks;
    const int ppb_lo      = total_pairs / grid;
    const int extra       = total_pairs - ppb_lo * grid;

    sdf_kernel<<<grid, THREADS>>>(points, v, vn, sr, out,
                                  total_points, P, N, ppb_lo, extra);
}